// round 15
// baseline (speedup 1.0000x reference)
#include <cuda_runtime.h>
#include <cuda_fp16.h>
#include <cstdint>

// ============================================================================
// CIN fused kernel, GB300 sm_103 (mma.sync + ldmatrix; tcgen05 unavailable
// under plain sm_103 ptxas target — cp.async.bulk + mbarrier ARE baseline).
// Per CTA (4 batches): out[n,o] = sum_k Zt[n,k] * W[o,k],  k=(h,m), n=(bl,d)
//   A = Zt in REGISTERS: half2 x0 (resident) * h broadcast via HMUL2
//   B = W chunks PRE-PACKED in gmem; ONE cp.async.bulk per chunk ->
//       7-stage mbarrier ring, NO per-chunk CTA barrier.
//   Consumer full-wait for chunk gc+1 HOISTED before the last MMA quarter of
//   chunk gc (overlaps TRYWAIT latency with tensor work). h prefetched 1 ahead.
// K-chunk = 64. Warp tile: 32 n x 64 o. Grid 128 x 512.
// ============================================================================

#define DEVINL __device__ __forceinline__

constexpr int THREADS = 512;
constexpr int NCTA    = 128;
constexpr int NCH64   = 16 + 64 + 64;     // 144 k-chunks of 64
constexpr int NSTAGE  = 7;
constexpr int CHUNK_B = 20480;            // bytes per packed chunk (smem image)
constexpr int CHUNK_H = CHUNK_B / 2;      // halfs per chunk

// smem layout (bytes)
constexpr int SM_FULL  = 0;                    // 7 x 8B mbarriers
constexpr int SM_EMPTY = 64;                   // 7 x 8B mbarriers
constexpr int SM_SCORE = 128;                  // 4 floats
constexpr int SM_BIAS  = 192;                  // 384 floats
constexpr int SM_LW    = 1728;                 // 384 floats
constexpr int SM_W     = 3264;                 // 7 stages x 20480 (16B aligned)
constexpr int SM_H     = SM_W + NSTAGE * CHUNK_B;       // 146624
constexpr int H_ROWH   = 132;                  // halfs per h row (264B, pad)
constexpr int SMEM_BYTES = SM_H + 256 * H_ROWH * 2;     // 214208

// device scratch: packed fp16 W chunks (exact smem image incl. 80B-row pad)
__device__ __align__(16) __half g_Wp[NCH64 * CHUNK_H];   // ~2.95 MB

// ---------------- helpers ----------------
DEVINL uint32_t smem_u32(const void* p) {
    uint32_t a;
    asm("{ .reg .u64 t; cvta.to.shared.u64 t, %1; cvt.u32.u64 %0, t; }"
        : "=r"(a) : "l"(p));
    return a;
}

DEVINL uint32_t h2u(__half2 v) { return *reinterpret_cast<uint32_t*>(&v); }

DEVINL void ldsm_x4(uint32_t* b, uint32_t addr) {
    asm volatile("ldmatrix.sync.aligned.m8n8.x4.shared.b16 {%0,%1,%2,%3}, [%4];"
                 : "=r"(b[0]), "=r"(b[1]), "=r"(b[2]), "=r"(b[3]) : "r"(addr));
}

DEVINL void mma16816(float* c, uint32_t a0, uint32_t a1, uint32_t a2, uint32_t a3,
                     uint32_t b0, uint32_t b1) {
    asm("mma.sync.aligned.m16n8k16.row.col.f32.f16.f16.f32 "
        "{%0,%1,%2,%3}, {%4,%5,%6,%7}, {%8,%9}, {%0,%1,%2,%3};"
        : "+f"(c[0]), "+f"(c[1]), "+f"(c[2]), "+f"(c[3])
        : "r"(a0), "r"(a1), "r"(a2), "r"(a3), "r"(b0), "r"(b1));
}

#define MBAR_INIT(addr, cnt) \
    asm volatile("mbarrier.init.shared.b64 [%0], %1;" \
                 :: "r"(addr), "r"((uint32_t)(cnt)) : "memory")

#define MBAR_EXPECT_TX(addr, bytes) \
    asm volatile("mbarrier.arrive.expect_tx.shared.b64 _, [%0], %1;" \
                 :: "r"(addr), "r"((uint32_t)(bytes)) : "memory")

#define MBAR_ARRIVE(addr) \
    asm volatile("mbarrier.arrive.shared.b64 _, [%0];" \
                 :: "r"(addr) : "memory")

#define MBAR_WAIT(addr, parity) do {                                           \
    uint32_t _m = (addr); uint32_t _p = (uint32_t)(parity); uint32_t _done;    \
    asm volatile("{\n\t.reg .pred p;\n\t"                                      \
        "mbarrier.try_wait.parity.acquire.cta.shared::cta.b64 p, [%1], %2;\n\t"\
        "selp.b32 %0, 1, 0, p;\n\t}"                                           \
        : "=r"(_done) : "r"(_m), "r"(_p) : "memory");                          \
    if (!_done) {                                                              \
        asm volatile("{\n\t.reg .pred P1;\n\t"                                 \
            "WL_%=:\n\t"                                                       \
            "mbarrier.try_wait.parity.acquire.cta.shared::cta.b64 P1, [%0], %1, 0x989680;\n\t" \
            "@P1 bra.uni WD_%=;\n\t"                                           \
            "bra.uni WL_%=;\n\t"                                               \
            "WD_%=:\n\t}" :: "r"(_m), "r"(_p) : "memory");                     \
    }                                                                          \
} while (0)

DEVINL void bulk_copy(uint32_t dst_smem, const void* src, uint32_t mbar) {
    asm volatile(
        "cp.async.bulk.shared::cluster.global.mbarrier::complete_tx::bytes "
        "[%0], [%1], %2, [%3];"
        :: "r"(dst_smem), "l"(src), "r"((uint32_t)CHUNK_B), "r"(mbar)
        : "memory");
}

// ============================================================================
// prep: pack fp32 W -> fp16 chunk images (80B rows: 64B data + 16B pad)
// ============================================================================
__global__ void cin_pack(const float* __restrict__ W0,
                         const float* __restrict__ W1,
                         const float* __restrict__ W2) {
    int e = blockIdx.x * blockDim.x + threadIdx.x;      // half index
    if (e >= NCH64 * CHUNK_H) return;
    int gc   = e / CHUNK_H;
    int byte = (e % CHUNK_H) * 2;
    int sub  = byte / 10240;          // 0 or 1 (32-k sub-chunk)
    int rem  = byte % 10240;
    int row  = rem / 80;
    int rb   = rem % 80;
    __half v = __float2half_rn(0.0f);
    if (rb < 64) {
        int kidx = rb >> 1;
        const float* W; int kw, c0;
        if (gc < 16)      { W = W0; kw = 1024; c0 = gc * 64; }
        else if (gc < 80) { W = W1; kw = 4096; c0 = (gc - 16) * 64; }
        else              { W = W2; kw = 4096; c0 = (gc - 80) * 64; }
        v = __float2half_rn(W[(size_t)row * kw + c0 + sub * 32 + kidx]);
    }
    g_Wp[e] = v;
}

// ============================================================================
// main fused kernel: 1 CTA = 4 batches (256 n-rows x 128 o), 3 layers + score
// ============================================================================
__global__ __launch_bounds__(THREADS, 1)
void cin_main(const float* __restrict__ x0g,
              const float* __restrict__ bias0,
              const float* __restrict__ bias1,
              const float* __restrict__ bias2,
              const float* __restrict__ lwp,
              const float* __restrict__ lbp,
              float* __restrict__ outp) {
    extern __shared__ char smemc[];
    const uint32_t sb = smem_u32(smemc);
    const int tid  = threadIdx.x;
    const int w    = tid >> 5;
    const int lane = tid & 31;
    const int b_base = blockIdx.x * 4;

    // mbarrier init: full count=1 (+tx), empty count=16 (one per warp)
    if (tid == 0) {
#pragma unroll
        for (int s = 0; s < NSTAGE; s++) {
            MBAR_INIT(sb + SM_FULL  + 8 * s, 1);
            MBAR_INIT(sb + SM_EMPTY + 8 * s, 16);
        }
    }
    __syncthreads();   // mbarriers visible before any produce

    // producer prologue (warp 0): issue chunks 0..NSTAGE-2
    if (w == 0) {
#pragma unroll
        for (int pg = 0; pg < NSTAGE - 1; pg++) {
            MBAR_WAIT(sb + SM_EMPTY + 8 * pg, 1);   // passes immediately
            if (lane == 0) {
                MBAR_EXPECT_TX(sb + SM_FULL + 8 * pg, CHUNK_B);
                bulk_copy(sb + SM_W + (uint32_t)pg * CHUNK_B,
                          g_Wp + (size_t)pg * CHUNK_H, sb + SM_FULL + 8 * pg);
            }
        }
    }

    // bias / lw to smem
    {
        const float* bptrs[3] = { bias0, bias1, bias2 };
        float* biasS = (float*)(smemc + SM_BIAS);
        float* lwS   = (float*)(smemc + SM_LW);
        for (int i = tid; i < 384; i += THREADS) {
            biasS[i] = bptrs[i >> 7][i & 127];
            lwS[i]   = lwp[i];
        }
    }
    if (tid < 4) ((float*)(smemc + SM_SCORE))[tid] = 0.0f;

    __half* hS = (__half*)(smemc + SM_H);
    // layer-0 h (fp16): h[n][m] = x0[bl][m][d],  n = bl*64 + d
    for (int i = tid; i < 256 * 32; i += THREADS) {
        int m = i >> 8, n = i & 255;
        hS[(size_t)n * H_ROWH + m] = __float2half_rn(
            x0g[(((size_t)(b_base + (n >> 6))) * 32 + m) * 64 + (n & 63)]);
    }

    // ---- per-thread geometry ----
    const int wn = w & 7;           // n block (32 rows)
    const int wo = w >> 3;          // o half (64 outputs)
    const int r  = lane >> 2;
    const int q  = lane & 3;
    const int bl = wn >> 1;
    const int dbase = ((wn & 1) << 5) + r;

    // x0 as half2 registers: x0h[j][i] = {x0[2q+8i], x0[2q+8i+1]} at d_j
    __half2 x0h[4][4];
    {
        const float* xb = x0g + ((size_t)(b_base + bl) * 32) * 64;
#pragma unroll
        for (int j = 0; j < 4; j++) {
            int dj = dbase + 8 * j;
#pragma unroll
            for (int i = 0; i < 4; i++) {
                int m = 2 * q + 8 * i;
                x0h[j][i] = __floats2half2_rn(xb[(size_t)m * 64 + dj],
                                              xb[(size_t)(m + 1) * 64 + dj]);
            }
        }
    }

    // h row pointers (rows n_j = 32*wn + r + 8j), fp16 rows
    __half* hrow0 = hS + (size_t)(32 * wn + r) * H_ROWH;
    __half* hrow1 = hrow0 + 8 * H_ROWH;
    __half* hrow2 = hrow0 + 16 * H_ROWH;
    __half* hrow3 = hrow0 + 24 * H_ROWH;

    // ldmatrix fragment base (within this warp's 64-o half)
    const int mi = lane >> 3;
    const uint32_t lm_base = (uint32_t)(wo * 5120 +
                             ((mi >> 1) * 8 + (lane & 7)) * 80 + (mi & 1) * 16);

    float acc[16][4];
#pragma unroll
    for (int t = 0; t < 16; t++)
#pragma unroll
        for (int c = 0; c < 4; c++) acc[t][c] = 0.0f;

    float score = 0.0f;
    int gc = 0;
    int cs = 0, cpar = 0;          // consumer cursor
    __syncthreads();   // h init + score init visible

    // wait for the very first chunk (subsequent waits are hoisted in-loop)
    MBAR_WAIT(sb + SM_FULL + 8 * cs, cpar);

    for (int lay = 0; lay < 3; lay++) {
        const int nch = (lay == 0) ? 16 : 64;

        // prefetch h pair for ch = 0 (h is valid: sync'd above / after epilogue)
        uint32_t hv0 = *(const uint32_t*)(hrow0);
        uint32_t hv1 = *(const uint32_t*)(hrow1);
        uint32_t hv2 = *(const uint32_t*)(hrow2);
        uint32_t hv3 = *(const uint32_t*)(hrow3);

        for (int ch = 0; ch < nch; ch++, gc++) {
            // chunk gc's full barrier already waited (prologue or hoist below)
            const uint32_t wbu = sb + SM_W + (uint32_t)cs * CHUNK_B + lm_base;

            // broadcast h (prefetched) for this chunk's two k-rows, 4 n-rows
            __half2 p0 = *reinterpret_cast<__half2*>(&hv0);
            __half2 p1 = *reinterpret_cast<__half2*>(&hv1);
            __half2 p2 = *reinterpret_cast<__half2*>(&hv2);
            __half2 p3 = *reinterpret_cast<__half2*>(&hv3);
            __half2 hb[4][2];
            hb[0][0] = __half2half2(__low2half(p0));
            hb[0][1] = __half2half2(__high2half(p0));
            hb[1][0] = __half2half2(__low2half(p1));
            hb[1][1] = __half2half2(__high2half(p1));
            hb[2][0] = __half2half2(__low2half(p2));
            hb[2][1] = __half2half2(__high2half(p2));
            hb[3][0] = __half2half2(__low2half(p3));
            hb[3][1] = __half2half2(__high2half(p3));

            // prefetch h pair for ch+1 (covered by the mma stream below)
            if (ch + 1 < nch) {
                hv0 = *(const uint32_t*)(hrow0 + 2 * (ch + 1));
                hv1 = *(const uint32_t*)(hrow1 + 2 * (ch + 1));
                hv2 = *(const uint32_t*)(hrow2 + 2 * (ch + 1));
                hv3 = *(const uint32_t*)(hrow3 + 2 * (ch + 1));
            }

            // MMA quarters sp = 0..2
#pragma unroll
            for (int sp = 0; sp < 3; sp++) {
                const int sub = sp >> 1;     // which k-row of the pair
                const int sh  = sp & 1;      // m half: [0,16) or [16,32)
                uint32_t a00 = h2u(__hmul2(hb[0][sub], x0h[0][2 * sh]));
                uint32_t a01 = h2u(__hmul2(hb[1][sub], x0h[1][2 * sh]));
                uint32_t a02 = h2u(__hmul2(hb[0][sub], x0h[0][2 * sh + 1]));
                uint32_t a03 = h2u(__hmul2(hb[1][sub], x0h[1][2 * sh + 1]));
                uint32_t a10 = h2u(__hmul2(hb[2][sub], x0h[2][2 * sh]));
                uint32_t a11 = h2u(__hmul2(hb[3][sub], x0h[3][2 * sh]));
                uint32_t a12 = h2u(__hmul2(hb[2][sub], x0h[2][2 * sh + 1]));
                uint32_t a13 = h2u(__hmul2(hb[3][sub], x0h[3][2 * sh + 1]));
                const uint32_t lma = wbu + (uint32_t)sub * 10240u +
                                     (uint32_t)sh * 32u;
#pragma unroll
                for (int g = 0; g < 4; g++) {
                    uint32_t b[4];
                    ldsm_x4(b, lma + (uint32_t)g * 1280);
                    mma16816(acc[2 * g],         a00, a01, a02, a03, b[0], b[1]);
                    mma16816(acc[2 * g + 1],     a00, a01, a02, a03, b[2], b[3]);
                    mma16816(acc[8 + 2 * g],     a10, a11, a12, a13, b[0], b[1]);
                    mma16816(acc[8 + 2 * g + 1], a10, a11, a12, a13, b[2], b[3]);
                }
            }

            // HOISTED wait for chunk gc+1 — overlapped by the sp=3 MMAs below
            const int ns   = (cs + 1 == NSTAGE) ? 0 : cs + 1;
            const int npar = (cs + 1 == NSTAGE) ? (cpar ^ 1) : cpar;
            if (gc + 1 < NCH64) MBAR_WAIT(sb + SM_FULL + 8 * ns, npar);

            // last MMA quarter sp = 3 (sub=1, sh=1)
            {
                uint32_t a00 = h2u(__hmul2(hb[0][1], x0h[0][2]));
                uint32_t a01 = h2u(__hmul2(hb[1][1], x0h[1][2]));
                uint32_t a02 = h2u(__hmul2(hb[0][1], x0h[0][3]));
                uint32_t a03 = h2u(__hmul2(hb[1][1], x0h[1][3]));
                uint32_t a10 = h2u(__hmul2(hb[2][1], x0h[2][2]));
                uint32_t a11 = h2u(__hmul2(hb[3][1], x0h[3][2]));
                uint32_t a12 = h2u(__hmul2(hb[2][1], x0h[2][3]));
                uint32_t a13 = h2u(__hmul2(hb[3][1], x0h[3][3]));
                const uint32_t lma = wbu + 10240u + 32u;
#pragma unroll
                for (int g = 0; g < 4; g++) {
                    uint32_t b[4];
                    ldsm_x4(b, lma + (uint32_t)g * 1280);
                    mma16816(acc[2 * g],         a00, a01, a02, a03, b[0], b[1]);
                    mma16816(acc[2 * g + 1],     a00, a01, a02, a03, b[2], b[3]);
                    mma16816(acc[8 + 2 * g],     a10, a11, a12, a13, b[0], b[1]);
                    mma16816(acc[8 + 2 * g + 1], a10, a11, a12, a13, b[2], b[3]);
                }
            }

            // done with this stage
            if (lane == 0) MBAR_ARRIVE(sb + SM_EMPTY + 8 * cs);
            cs = ns; cpar = npar;

            // ---- producer (rotating, post-compute): chunk gc+NSTAGE-1 ----
            if (w == (gc & 15)) {
                const int pg = gc + NSTAGE - 1;
                if (pg < NCH64) {
                    const int pps  = pg % NSTAGE;
                    const int ppp  = ((pg / NSTAGE) & 1) ^ 1;
                    MBAR_WAIT(sb + SM_EMPTY + 8 * pps, ppp);
                    if (lane == 0) {
                        MBAR_EXPECT_TX(sb + SM_FULL + 8 * pps, CHUNK_B);
                        bulk_copy(sb + SM_W + (uint32_t)pps * CHUNK_B,
                                  g_Wp + (size_t)pg * CHUNK_H,
                                  sb + SM_FULL + 8 * pps);
                    }
                }
            }
        }

        // -------- epilogue --------
        __syncthreads();   // all warps done reading h for this layer
        {
            const float* biasS = (const float*)(smemc + SM_BIAS) + lay * 128;
            const float* lwS   = (const float*)(smemc + SM_LW) + lay * 128;
            float sc = 0.0f;
#pragma unroll
            for (int T = 0; T < 2; T++) {
                __half* ha  = T ? hrow2 : hrow0;
                __half* hc  = T ? hrow3 : hrow1;
#pragma unroll
                for (int go = 0; go < 8; go++) {
                    const int t = 8 * T + go;
                    const int o = 64 * wo + 8 * go + 2 * q;
                    const float bv0 = biasS[o], bv1 = biasS[o + 1];
                    float v00 = fmaxf(acc[t][0] + bv0, 0.0f);
                    float v01 = fmaxf(acc[t][1] + bv1, 0.0f);
                    float v10 = fmaxf(acc[t][2] + bv0, 0.0f);
                    float v11 = fmaxf(acc[t][3] + bv1, 0.0f);
                    sc += (v00 + v10) * lwS[o] + (v01 + v11) * lwS[o + 1];
                    if (lay < 2) {
                        *(__half2*)(ha + o) = __floats2half2_rn(v00, v01);
                        *(__half2*)(hc + o) = __floats2half2_rn(v10, v11);
                    }
                    acc[t][0] = acc[t][1] = acc[t][2] = acc[t][3] = 0.0f;
                }
            }
            score += sc;
        }
        __syncthreads();   // new h visible before next layer's reads
    }

    // warp-reduce score, accumulate per-batch
#pragma unroll
    for (int off = 16; off; off >>= 1)
        score += __shfl_xor_sync(0xFFFFFFFFu, score, off);
    if (lane == 0) atomicAdd((float*)(smemc + SM_SCORE) + bl, score);
    __syncthreads();

    if (tid < 4) outp[b_base + tid] = ((float*)(smemc + SM_SCORE))[tid] + lbp[0];
}

extern "C" void kernel_launch(void* const* d_in, const int* in_sizes, int n_in,
                              void* d_out, int out_size) {
    const float* x0 = (const float*)d_in[0];
    const float* W0 = (const float*)d_in[1];
    const float* b0 = (const float*)d_in[2];
    const float* W1 = (const float*)d_in[3];
    const float* b1 = (const float*)d_in[4];
    const float* W2 = (const float*)d_in[5];
    const float* b2 = (const float*)d_in[6];
    const float* lw = (const float*)d_in[7];
    const float* lb = (const float*)d_in[8];
    float* outp = (float*)d_out;

    constexpr int TOTP = NCH64 * CHUNK_H;
    cin_pack<<<(TOTP + 255) / 256, 256>>>(W0, W1, W2);

    static_assert(SMEM_BYTES <= 227 * 1024, "smem");
    cudaFuncSetAttribute(cin_main, cudaFuncAttributeMaxDynamicSharedMemorySize,
                         SMEM_BYTES);
    cin_main<<<NCTA, THREADS, SMEM_BYTES>>>(x0, b0, b1, b2, lw, lb, outp);
}

// round 16
// speedup vs baseline: 1.0106x; 1.0106x over previous
#include <cuda_runtime.h>
#include <cuda_fp16.h>
#include <cstdint>

// ============================================================================
// CIN fused kernel, GB300 sm_103 — FINAL (best measured: 188.0 us).
// (mma.sync + ldmatrix; tcgen05 unavailable under plain sm_103 ptxas target —
//  cp.async.bulk + mbarrier ARE baseline PTX.)
// Per CTA (4 batches): out[n,o] = sum_k Zt[n,k] * W[o,k],  k=(h,m), n=(bl,d)
//   A = Zt in REGISTERS: half2 x0 (resident) * h broadcast via HMUL2
//   B = W chunks PRE-PACKED in gmem to the exact smem image; ONE
//       cp.async.bulk per chunk -> 7-stage mbarrier ring, NO per-chunk
//       CTA barrier. Warp 0 produces (6 ahead); 16 warps consume freely.
//   h stored in SMEM as fp16 (numerically identical: A-build rounds anyway).
// K-chunk = 64. Warp tile: 32 n x 64 o. Grid 128 x 512.
// ============================================================================

#define DEVINL __device__ __forceinline__

constexpr int THREADS = 512;
constexpr int NCTA    = 128;
constexpr int NCH64   = 16 + 64 + 64;     // 144 k-chunks of 64
constexpr int NSTAGE  = 7;
constexpr int CHUNK_B = 20480;            // bytes per packed chunk (smem image)
constexpr int CHUNK_H = CHUNK_B / 2;      // halfs per chunk

// smem layout (bytes)
constexpr int SM_FULL  = 0;                    // 7 x 8B mbarriers
constexpr int SM_EMPTY = 64;                   // 7 x 8B mbarriers
constexpr int SM_SCORE = 128;                  // 4 floats
constexpr int SM_BIAS  = 192;                  // 384 floats
constexpr int SM_LW    = 1728;                 // 384 floats
constexpr int SM_W     = 3264;                 // 7 stages x 20480 (16B aligned)
constexpr int SM_H     = SM_W + NSTAGE * CHUNK_B;       // 146624
constexpr int H_ROWH   = 132;                  // halfs per h row (264B, pad)
constexpr int SMEM_BYTES = SM_H + 256 * H_ROWH * 2;     // 214208

// device scratch: packed fp16 W chunks (exact smem image incl. 80B-row pad)
__device__ __align__(16) __half g_Wp[NCH64 * CHUNK_H];   // ~2.95 MB

// ---------------- helpers ----------------
DEVINL uint32_t smem_u32(const void* p) {
    uint32_t a;
    asm("{ .reg .u64 t; cvta.to.shared.u64 t, %1; cvt.u32.u64 %0, t; }"
        : "=r"(a) : "l"(p));
    return a;
}

DEVINL uint32_t h2u(__half2 v) { return *reinterpret_cast<uint32_t*>(&v); }

DEVINL void ldsm_x4(uint32_t* b, uint32_t addr) {
    asm volatile("ldmatrix.sync.aligned.m8n8.x4.shared.b16 {%0,%1,%2,%3}, [%4];"
                 : "=r"(b[0]), "=r"(b[1]), "=r"(b[2]), "=r"(b[3]) : "r"(addr));
}

DEVINL void mma16816(float* c, uint32_t a0, uint32_t a1, uint32_t a2, uint32_t a3,
                     uint32_t b0, uint32_t b1) {
    asm("mma.sync.aligned.m16n8k16.row.col.f32.f16.f16.f32 "
        "{%0,%1,%2,%3}, {%4,%5,%6,%7}, {%8,%9}, {%0,%1,%2,%3};"
        : "+f"(c[0]), "+f"(c[1]), "+f"(c[2]), "+f"(c[3])
        : "r"(a0), "r"(a1), "r"(a2), "r"(a3), "r"(b0), "r"(b1));
}

#define MBAR_INIT(addr, cnt) \
    asm volatile("mbarrier.init.shared.b64 [%0], %1;" \
                 :: "r"(addr), "r"((uint32_t)(cnt)) : "memory")

#define MBAR_EXPECT_TX(addr, bytes) \
    asm volatile("mbarrier.arrive.expect_tx.shared.b64 _, [%0], %1;" \
                 :: "r"(addr), "r"((uint32_t)(bytes)) : "memory")

#define MBAR_ARRIVE(addr) \
    asm volatile("mbarrier.arrive.shared.b64 _, [%0];" \
                 :: "r"(addr) : "memory")

#define MBAR_WAIT(addr, parity) do {                                           \
    uint32_t _m = (addr); uint32_t _p = (uint32_t)(parity); uint32_t _done;    \
    asm volatile("{\n\t.reg .pred p;\n\t"                                      \
        "mbarrier.try_wait.parity.acquire.cta.shared::cta.b64 p, [%1], %2;\n\t"\
        "selp.b32 %0, 1, 0, p;\n\t}"                                           \
        : "=r"(_done) : "r"(_m), "r"(_p) : "memory");                          \
    if (!_done) {                                                              \
        asm volatile("{\n\t.reg .pred P1;\n\t"                                 \
            "WL_%=:\n\t"                                                       \
            "mbarrier.try_wait.parity.acquire.cta.shared::cta.b64 P1, [%0], %1, 0x989680;\n\t" \
            "@P1 bra.uni WD_%=;\n\t"                                           \
            "bra.uni WL_%=;\n\t"                                               \
            "WD_%=:\n\t}" :: "r"(_m), "r"(_p) : "memory");                     \
    }                                                                          \
} while (0)

DEVINL void bulk_copy(uint32_t dst_smem, const void* src, uint32_t mbar) {
    asm volatile(
        "cp.async.bulk.shared::cluster.global.mbarrier::complete_tx::bytes "
        "[%0], [%1], %2, [%3];"
        :: "r"(dst_smem), "l"(src), "r"((uint32_t)CHUNK_B), "r"(mbar)
        : "memory");
}

// ============================================================================
// prep: pack fp32 W -> fp16 chunk images (80B rows: 64B data + 16B pad)
// ============================================================================
__global__ void cin_pack(const float* __restrict__ W0,
                         const float* __restrict__ W1,
                         const float* __restrict__ W2) {
    int e = blockIdx.x * blockDim.x + threadIdx.x;      // half index
    if (e >= NCH64 * CHUNK_H) return;
    int gc   = e / CHUNK_H;
    int byte = (e % CHUNK_H) * 2;
    int sub  = byte / 10240;          // 0 or 1 (32-k sub-chunk)
    int rem  = byte % 10240;
    int row  = rem / 80;
    int rb   = rem % 80;
    __half v = __float2half_rn(0.0f);
    if (rb < 64) {
        int kidx = rb >> 1;
        const float* W; int kw, c0;
        if (gc < 16)      { W = W0; kw = 1024; c0 = gc * 64; }
        else if (gc < 80) { W = W1; kw = 4096; c0 = (gc - 16) * 64; }
        else              { W = W2; kw = 4096; c0 = (gc - 80) * 64; }
        v = __float2half_rn(W[(size_t)row * kw + c0 + sub * 32 + kidx]);
    }
    g_Wp[e] = v;
}

// ============================================================================
// main fused kernel: 1 CTA = 4 batches (256 n-rows x 128 o), 3 layers + score
// ============================================================================
__global__ __launch_bounds__(THREADS, 1)
void cin_main(const float* __restrict__ x0g,
              const float* __restrict__ bias0,
              const float* __restrict__ bias1,
              const float* __restrict__ bias2,
              const float* __restrict__ lwp,
              const float* __restrict__ lbp,
              float* __restrict__ outp) {
    extern __shared__ char smemc[];
    const uint32_t sb = smem_u32(smemc);
    const int tid  = threadIdx.x;
    const int w    = tid >> 5;
    const int lane = tid & 31;
    const int b_base = blockIdx.x * 4;

    // mbarrier init: full count=1 (+tx), empty count=16 (one per warp)
    if (tid == 0) {
#pragma unroll
        for (int s = 0; s < NSTAGE; s++) {
            MBAR_INIT(sb + SM_FULL  + 8 * s, 1);
            MBAR_INIT(sb + SM_EMPTY + 8 * s, 16);
        }
    }
    __syncthreads();   // mbarriers visible before any produce

    // producer cursor (warp 0 only uses it)
    int ps = 0, ppar = 1;
    if (w == 0) {
#pragma unroll
        for (int pg = 0; pg < NSTAGE - 1; pg++) {
            MBAR_WAIT(sb + SM_EMPTY + 8 * ps, ppar);   // passes immediately
            if (lane == 0) {
                MBAR_EXPECT_TX(sb + SM_FULL + 8 * ps, CHUNK_B);
                bulk_copy(sb + SM_W + (uint32_t)ps * CHUNK_B,
                          g_Wp + (size_t)pg * CHUNK_H, sb + SM_FULL + 8 * ps);
            }
            if (++ps == NSTAGE) { ps = 0; ppar ^= 1; }
        }
    }

    // bias / lw to smem
    {
        const float* bptrs[3] = { bias0, bias1, bias2 };
        float* biasS = (float*)(smemc + SM_BIAS);
        float* lwS   = (float*)(smemc + SM_LW);
        for (int i = tid; i < 384; i += THREADS) {
            biasS[i] = bptrs[i >> 7][i & 127];
            lwS[i]   = lwp[i];
        }
    }
    if (tid < 4) ((float*)(smemc + SM_SCORE))[tid] = 0.0f;

    __half* hS = (__half*)(smemc + SM_H);
    // layer-0 h (fp16): h[n][m] = x0[bl][m][d],  n = bl*64 + d
    for (int i = tid; i < 256 * 32; i += THREADS) {
        int m = i >> 8, n = i & 255;
        hS[(size_t)n * H_ROWH + m] = __float2half_rn(
            x0g[(((size_t)(b_base + (n >> 6))) * 32 + m) * 64 + (n & 63)]);
    }

    // ---- per-thread geometry ----
    const int wn = w & 7;           // n block (32 rows)
    const int wo = w >> 3;          // o half (64 outputs)
    const int r  = lane >> 2;
    const int q  = lane & 3;
    const int bl = wn >> 1;
    const int dbase = ((wn & 1) << 5) + r;

    // x0 as half2 registers: x0h[j][i] = {x0[2q+8i], x0[2q+8i+1]} at d_j
    __half2 x0h[4][4];
    {
        const float* xb = x0g + ((size_t)(b_base + bl) * 32) * 64;
#pragma unroll
        for (int j = 0; j < 4; j++) {
            int dj = dbase + 8 * j;
#pragma unroll
            for (int i = 0; i < 4; i++) {
                int m = 2 * q + 8 * i;
                x0h[j][i] = __floats2half2_rn(xb[(size_t)m * 64 + dj],
                                              xb[(size_t)(m + 1) * 64 + dj]);
            }
        }
    }

    // h row pointers (rows n_j = 32*wn + r + 8j), fp16 rows
    __half* hrow0 = hS + (size_t)(32 * wn + r) * H_ROWH;
    __half* hrow1 = hrow0 + 8 * H_ROWH;
    __half* hrow2 = hrow0 + 16 * H_ROWH;
    __half* hrow3 = hrow0 + 24 * H_ROWH;

    // ldmatrix fragment base (within this warp's 64-o half)
    const int mi = lane >> 3;
    const uint32_t lm_base = (uint32_t)(wo * 5120 +
                             ((mi >> 1) * 8 + (lane & 7)) * 80 + (mi & 1) * 16);

    float acc[16][4];
#pragma unroll
    for (int t = 0; t < 16; t++)
#pragma unroll
        for (int c = 0; c < 4; c++) acc[t][c] = 0.0f;

    float score = 0.0f;
    int gc = 0;
    int cs = 0, cpar = 0;          // consumer cursor
    __syncthreads();   // h init + score init visible

    for (int lay = 0; lay < 3; lay++) {
        const int nch = (lay == 0) ? 16 : 64;
        for (int ch = 0; ch < nch; ch++, gc++) {
            // ---- producer (warp 0): issue chunk gc+NSTAGE-1 ----
            if (w == 0) {
                const int pg = gc + NSTAGE - 1;
                if (pg < NCH64) {
                    MBAR_WAIT(sb + SM_EMPTY + 8 * ps, ppar);
                    if (lane == 0) {
                        MBAR_EXPECT_TX(sb + SM_FULL + 8 * ps, CHUNK_B);
                        bulk_copy(sb + SM_W + (uint32_t)ps * CHUNK_B,
                                  g_Wp + (size_t)pg * CHUNK_H,
                                  sb + SM_FULL + 8 * ps);
                    }
                    if (++ps == NSTAGE) { ps = 0; ppar ^= 1; }
                }
            }

            // ---- consumer: wait chunk gc ----
            MBAR_WAIT(sb + SM_FULL + 8 * cs, cpar);
            const uint32_t wbu = sb + SM_W + (uint32_t)cs * CHUNK_B + lm_base;

            // h values (fp16) for this chunk's two k-rows, 4 n-rows
            uint32_t hv0 = *(const uint32_t*)(hrow0 + 2 * ch);
            uint32_t hv1 = *(const uint32_t*)(hrow1 + 2 * ch);
            uint32_t hv2 = *(const uint32_t*)(hrow2 + 2 * ch);
            uint32_t hv3 = *(const uint32_t*)(hrow3 + 2 * ch);
            __half2 p0 = *reinterpret_cast<__half2*>(&hv0);
            __half2 p1 = *reinterpret_cast<__half2*>(&hv1);
            __half2 p2 = *reinterpret_cast<__half2*>(&hv2);
            __half2 p3 = *reinterpret_cast<__half2*>(&hv3);
            __half2 hb[4][2];
            hb[0][0] = __half2half2(__low2half(p0));
            hb[0][1] = __half2half2(__high2half(p0));
            hb[1][0] = __half2half2(__low2half(p1));
            hb[1][1] = __half2half2(__high2half(p1));
            hb[2][0] = __half2half2(__low2half(p2));
            hb[2][1] = __half2half2(__high2half(p2));
            hb[3][0] = __half2half2(__low2half(p3));
            hb[3][1] = __half2half2(__high2half(p3));

#pragma unroll
            for (int sp = 0; sp < 4; sp++) {
                const int sub = sp >> 1;     // which k-row of the pair
                const int sh  = sp & 1;      // m half: [0,16) or [16,32)
                uint32_t a00 = h2u(__hmul2(hb[0][sub], x0h[0][2 * sh]));
                uint32_t a01 = h2u(__hmul2(hb[1][sub], x0h[1][2 * sh]));
                uint32_t a02 = h2u(__hmul2(hb[0][sub], x0h[0][2 * sh + 1]));
                uint32_t a03 = h2u(__hmul2(hb[1][sub], x0h[1][2 * sh + 1]));
                uint32_t a10 = h2u(__hmul2(hb[2][sub], x0h[2][2 * sh]));
                uint32_t a11 = h2u(__hmul2(hb[3][sub], x0h[3][2 * sh]));
                uint32_t a12 = h2u(__hmul2(hb[2][sub], x0h[2][2 * sh + 1]));
                uint32_t a13 = h2u(__hmul2(hb[3][sub], x0h[3][2 * sh + 1]));
                const uint32_t lma = wbu + (uint32_t)sub * 10240u +
                                     (uint32_t)sh * 32u;
#pragma unroll
                for (int g = 0; g < 4; g++) {
                    uint32_t b[4];
                    ldsm_x4(b, lma + (uint32_t)g * 1280);
                    mma16816(acc[2 * g],         a00, a01, a02, a03, b[0], b[1]);
                    mma16816(acc[2 * g + 1],     a00, a01, a02, a03, b[2], b[3]);
                    mma16816(acc[8 + 2 * g],     a10, a11, a12, a13, b[0], b[1]);
                    mma16816(acc[8 + 2 * g + 1], a10, a11, a12, a13, b[2], b[3]);
                }
            }

            // done with this stage
            if (lane == 0) MBAR_ARRIVE(sb + SM_EMPTY + 8 * cs);
            if (++cs == NSTAGE) { cs = 0; cpar ^= 1; }
        }

        // -------- epilogue --------
        __syncthreads();   // all warps done reading h for this layer
        {
            const float* biasS = (const float*)(smemc + SM_BIAS) + lay * 128;
            const float* lwS   = (const float*)(smemc + SM_LW) + lay * 128;
            float sc = 0.0f;
#pragma unroll
            for (int T = 0; T < 2; T++) {
                __half* ha  = T ? hrow2 : hrow0;
                __half* hc  = T ? hrow3 : hrow1;
#pragma unroll
                for (int go = 0; go < 8; go++) {
                    const int t = 8 * T + go;
                    const int o = 64 * wo + 8 * go + 2 * q;
                    const float bv0 = biasS[o], bv1 = biasS[o + 1];
                    float v00 = fmaxf(acc[t][0] + bv0, 0.0f);
                    float v01 = fmaxf(acc[t][1] + bv1, 0.0f);
                    float v10 = fmaxf(acc[t][2] + bv0, 0.0f);
                    float v11 = fmaxf(acc[t][3] + bv1, 0.0f);
                    sc += (v00 + v10) * lwS[o] + (v01 + v11) * lwS[o + 1];
                    if (lay < 2) {
                        *(__half2*)(ha + o) = __floats2half2_rn(v00, v01);
                        *(__half2*)(hc + o) = __floats2half2_rn(v10, v11);
                    }
                    acc[t][0] = acc[t][1] = acc[t][2] = acc[t][3] = 0.0f;
                }
            }
            score += sc;
        }
        __syncthreads();   // new h visible before next layer's reads
    }

    // warp-reduce score, accumulate per-batch
#pragma unroll
    for (int off = 16; off; off >>= 1)
        score += __shfl_xor_sync(0xFFFFFFFFu, score, off);
    if (lane == 0) atomicAdd((float*)(smemc + SM_SCORE) + bl, score);
    __syncthreads();

    if (tid < 4) outp[b_base + tid] = ((float*)(smemc + SM_SCORE))[tid] + lbp[0];
}

extern "C" void kernel_launch(void* const* d_in, const int* in_sizes, int n_in,
                              void* d_out, int out_size) {
    const float* x0 = (const float*)d_in[0];
    const float* W0 = (const float*)d_in[1];
    const float* b0 = (const float*)d_in[2];
    const float* W1 = (const float*)d_in[3];
    const float* b1 = (const float*)d_in[4];
    const float* W2 = (const float*)d_in[5];
    const float* b2 = (const float*)d_in[6];
    const float* lw = (const float*)d_in[7];
    const float* lb = (const float*)d_in[8];
    float* outp = (float*)d_out;

    constexpr int TOTP = NCH64 * CHUNK_H;
    cin_pack<<<(TOTP + 255) / 256, 256>>>(W0, W1, W2);

    static_assert(SMEM_BYTES <= 227 * 1024, "smem");
    cudaFuncSetAttribute(cin_main, cudaFuncAttributeMaxDynamicSharedMemorySize,
                         SMEM_BYTES);
    cin_main<<<NCTA, THREADS, SMEM_BYTES>>>(x0, b0, b1, b2, lw, lb, outp);
}

// round 17
// speedup vs baseline: 1.0209x; 1.0102x over previous
#include <cuda_runtime.h>
#include <cuda_fp16.h>
#include <cstdint>

// ============================================================================
// CIN fused kernel, GB300 sm_103 — best mainloop (186.9 us) + vectorized pack.
// (mma.sync + ldmatrix; tcgen05 unavailable under plain sm_103 ptxas target —
//  cp.async.bulk + mbarrier ARE baseline PTX.)
// Per CTA (4 batches): out[n,o] = sum_k Zt[n,k] * W[o,k],  k=(h,m), n=(bl,d)
//   A = Zt in REGISTERS: half2 x0 (resident) * h broadcast via HMUL2
//   B = W chunks PRE-PACKED in gmem to the exact smem image; ONE
//       cp.async.bulk per chunk -> 7-stage mbarrier ring, NO per-chunk
//       CTA barrier. Warp 0 produces (6 ahead); 16 warps consume freely.
//   h stored in SMEM as fp16 (numerically identical: A-build rounds anyway).
// K-chunk = 64. Warp tile: 32 n x 64 o. Grid 128 x 512.
// ============================================================================

#define DEVINL __device__ __forceinline__

constexpr int THREADS = 512;
constexpr int NCTA    = 128;
constexpr int NCH64   = 16 + 64 + 64;     // 144 k-chunks of 64
constexpr int NSTAGE  = 7;
constexpr int CHUNK_B = 20480;            // bytes per packed chunk (smem image)
constexpr int CHUNK_H = CHUNK_B / 2;      // halfs per chunk

// smem layout (bytes)
constexpr int SM_FULL  = 0;                    // 7 x 8B mbarriers
constexpr int SM_EMPTY = 64;                   // 7 x 8B mbarriers
constexpr int SM_SCORE = 128;                  // 4 floats
constexpr int SM_BIAS  = 192;                  // 384 floats
constexpr int SM_LW    = 1728;                 // 384 floats
constexpr int SM_W     = 3264;                 // 7 stages x 20480 (16B aligned)
constexpr int SM_H     = SM_W + NSTAGE * CHUNK_B;       // 146624
constexpr int H_ROWH   = 132;                  // halfs per h row (264B, pad)
constexpr int SMEM_BYTES = SM_H + 256 * H_ROWH * 2;     // 214208

// device scratch: packed fp16 W chunks (exact smem image incl. 80B-row pad)
__device__ __align__(16) __half g_Wp[NCH64 * CHUNK_H];   // ~2.95 MB

// ---------------- helpers ----------------
DEVINL uint32_t smem_u32(const void* p) {
    uint32_t a;
    asm("{ .reg .u64 t; cvta.to.shared.u64 t, %1; cvt.u32.u64 %0, t; }"
        : "=r"(a) : "l"(p));
    return a;
}

DEVINL uint32_t h2u(__half2 v) { return *reinterpret_cast<uint32_t*>(&v); }

DEVINL void ldsm_x4(uint32_t* b, uint32_t addr) {
    asm volatile("ldmatrix.sync.aligned.m8n8.x4.shared.b16 {%0,%1,%2,%3}, [%4];"
                 : "=r"(b[0]), "=r"(b[1]), "=r"(b[2]), "=r"(b[3]) : "r"(addr));
}

DEVINL void mma16816(float* c, uint32_t a0, uint32_t a1, uint32_t a2, uint32_t a3,
                     uint32_t b0, uint32_t b1) {
    asm("mma.sync.aligned.m16n8k16.row.col.f32.f16.f16.f32 "
        "{%0,%1,%2,%3}, {%4,%5,%6,%7}, {%8,%9}, {%0,%1,%2,%3};"
        : "+f"(c[0]), "+f"(c[1]), "+f"(c[2]), "+f"(c[3])
        : "r"(a0), "r"(a1), "r"(a2), "r"(a3), "r"(b0), "r"(b1));
}

#define MBAR_INIT(addr, cnt) \
    asm volatile("mbarrier.init.shared.b64 [%0], %1;" \
                 :: "r"(addr), "r"((uint32_t)(cnt)) : "memory")

#define MBAR_EXPECT_TX(addr, bytes) \
    asm volatile("mbarrier.arrive.expect_tx.shared.b64 _, [%0], %1;" \
                 :: "r"(addr), "r"((uint32_t)(bytes)) : "memory")

#define MBAR_ARRIVE(addr) \
    asm volatile("mbarrier.arrive.shared.b64 _, [%0];" \
                 :: "r"(addr) : "memory")

#define MBAR_WAIT(addr, parity) do {                                           \
    uint32_t _m = (addr); uint32_t _p = (uint32_t)(parity); uint32_t _done;    \
    asm volatile("{\n\t.reg .pred p;\n\t"                                      \
        "mbarrier.try_wait.parity.acquire.cta.shared::cta.b64 p, [%1], %2;\n\t"\
        "selp.b32 %0, 1, 0, p;\n\t}"                                           \
        : "=r"(_done) : "r"(_m), "r"(_p) : "memory");                          \
    if (!_done) {                                                              \
        asm volatile("{\n\t.reg .pred P1;\n\t"                                 \
            "WL_%=:\n\t"                                                       \
            "mbarrier.try_wait.parity.acquire.cta.shared::cta.b64 P1, [%0], %1, 0x989680;\n\t" \
            "@P1 bra.uni WD_%=;\n\t"                                           \
            "bra.uni WL_%=;\n\t"                                               \
            "WD_%=:\n\t}" :: "r"(_m), "r"(_p) : "memory");                     \
    }                                                                          \
} while (0)

DEVINL void bulk_copy(uint32_t dst_smem, const void* src, uint32_t mbar) {
    asm volatile(
        "cp.async.bulk.shared::cluster.global.mbarrier::complete_tx::bytes "
        "[%0], [%1], %2, [%3];"
        :: "r"(dst_smem), "l"(src), "r"((uint32_t)CHUNK_B), "r"(mbar)
        : "memory");
}

// ============================================================================
// prep: pack fp32 W -> fp16 chunk images (80B rows: 64B data + 16B pad),
// VECTORIZED: one thread = one 16B uint4 (8 halfs), all within one row.
// Row layout: 80B = 5 x 16B slots; slots 0..3 = data (8 halfs each),
// slot 4 = pad (zeros). CHUNK_B/16 = 1280 uint4 per chunk.
// ============================================================================
__global__ void cin_pack(const float* __restrict__ W0,
                         const float* __restrict__ W1,
                         const float* __restrict__ W2) {
    int e = blockIdx.x * blockDim.x + threadIdx.x;      // uint4 index
    constexpr int TOTV = NCH64 * (CHUNK_B / 16);
    if (e >= TOTV) return;
    int gc  = e / (CHUNK_B / 16);
    int rem = e % (CHUNK_B / 16);
    int sub  = rem / 640;            // 0 or 1 (32-k sub-chunk, 640 uint4 each)
    int rrem = rem % 640;
    int row  = rrem / 5;             // 128 rows x 5 slots
    int slot = rrem % 5;

    uint4 out;
    if (slot == 4) {
        out = make_uint4(0u, 0u, 0u, 0u);           // pad
    } else {
        const float* W; int kw, c0;
        if (gc < 16)      { W = W0; kw = 1024; c0 = gc * 64; }
        else if (gc < 80) { W = W1; kw = 4096; c0 = (gc - 16) * 64; }
        else              { W = W2; kw = 4096; c0 = (gc - 80) * 64; }
        const float* src = W + (size_t)row * kw + c0 + sub * 32 + slot * 8;
        float4 f0 = *(const float4*)(src);
        float4 f1 = *(const float4*)(src + 4);
        out.x = h2u(__floats2half2_rn(f0.x, f0.y));
        out.y = h2u(__floats2half2_rn(f0.z, f0.w));
        out.z = h2u(__floats2half2_rn(f1.x, f1.y));
        out.w = h2u(__floats2half2_rn(f1.z, f1.w));
    }
    *(uint4*)((char*)g_Wp + (size_t)e * 16) = out;
}

// ============================================================================
// main fused kernel: 1 CTA = 4 batches (256 n-rows x 128 o), 3 layers + score
// ============================================================================
__global__ __launch_bounds__(THREADS, 1)
void cin_main(const float* __restrict__ x0g,
              const float* __restrict__ bias0,
              const float* __restrict__ bias1,
              const float* __restrict__ bias2,
              const float* __restrict__ lwp,
              const float* __restrict__ lbp,
              float* __restrict__ outp) {
    extern __shared__ char smemc[];
    const uint32_t sb = smem_u32(smemc);
    const int tid  = threadIdx.x;
    const int w    = tid >> 5;
    const int lane = tid & 31;
    const int b_base = blockIdx.x * 4;

    // mbarrier init: full count=1 (+tx), empty count=16 (one per warp)
    if (tid == 0) {
#pragma unroll
        for (int s = 0; s < NSTAGE; s++) {
            MBAR_INIT(sb + SM_FULL  + 8 * s, 1);
            MBAR_INIT(sb + SM_EMPTY + 8 * s, 16);
        }
    }
    __syncthreads();   // mbarriers visible before any produce

    // producer cursor (warp 0 only uses it)
    int ps = 0, ppar = 1;
    if (w == 0) {
#pragma unroll
        for (int pg = 0; pg < NSTAGE - 1; pg++) {
            MBAR_WAIT(sb + SM_EMPTY + 8 * ps, ppar);   // passes immediately
            if (lane == 0) {
                MBAR_EXPECT_TX(sb + SM_FULL + 8 * ps, CHUNK_B);
                bulk_copy(sb + SM_W + (uint32_t)ps * CHUNK_B,
                          g_Wp + (size_t)pg * CHUNK_H, sb + SM_FULL + 8 * ps);
            }
            if (++ps == NSTAGE) { ps = 0; ppar ^= 1; }
        }
    }

    // bias / lw to smem
    {
        const float* bptrs[3] = { bias0, bias1, bias2 };
        float* biasS = (float*)(smemc + SM_BIAS);
        float* lwS   = (float*)(smemc + SM_LW);
        for (int i = tid; i < 384; i += THREADS) {
            biasS[i] = bptrs[i >> 7][i & 127];
            lwS[i]   = lwp[i];
        }
    }
    if (tid < 4) ((float*)(smemc + SM_SCORE))[tid] = 0.0f;

    __half* hS = (__half*)(smemc + SM_H);
    // layer-0 h (fp16): h[n][m] = x0[bl][m][d],  n = bl*64 + d
    for (int i = tid; i < 256 * 32; i += THREADS) {
        int m = i >> 8, n = i & 255;
        hS[(size_t)n * H_ROWH + m] = __float2half_rn(
            x0g[(((size_t)(b_base + (n >> 6))) * 32 + m) * 64 + (n & 63)]);
    }

    // ---- per-thread geometry ----
    const int wn = w & 7;           // n block (32 rows)
    const int wo = w >> 3;          // o half (64 outputs)
    const int r  = lane >> 2;
    const int q  = lane & 3;
    const int bl = wn >> 1;
    const int dbase = ((wn & 1) << 5) + r;

    // x0 as half2 registers: x0h[j][i] = {x0[2q+8i], x0[2q+8i+1]} at d_j
    __half2 x0h[4][4];
    {
        const float* xb = x0g + ((size_t)(b_base + bl) * 32) * 64;
#pragma unroll
        for (int j = 0; j < 4; j++) {
            int dj = dbase + 8 * j;
#pragma unroll
            for (int i = 0; i < 4; i++) {
                int m = 2 * q + 8 * i;
                x0h[j][i] = __floats2half2_rn(xb[(size_t)m * 64 + dj],
                                              xb[(size_t)(m + 1) * 64 + dj]);
            }
        }
    }

    // h row pointers (rows n_j = 32*wn + r + 8j), fp16 rows
    __half* hrow0 = hS + (size_t)(32 * wn + r) * H_ROWH;
    __half* hrow1 = hrow0 + 8 * H_ROWH;
    __half* hrow2 = hrow0 + 16 * H_ROWH;
    __half* hrow3 = hrow0 + 24 * H_ROWH;

    // ldmatrix fragment base (within this warp's 64-o half)
    const int mi = lane >> 3;
    const uint32_t lm_base = (uint32_t)(wo * 5120 +
                             ((mi >> 1) * 8 + (lane & 7)) * 80 + (mi & 1) * 16);

    float acc[16][4];
#pragma unroll
    for (int t = 0; t < 16; t++)
#pragma unroll
        for (int c = 0; c < 4; c++) acc[t][c] = 0.0f;

    float score = 0.0f;
    int gc = 0;
    int cs = 0, cpar = 0;          // consumer cursor
    __syncthreads();   // h init + score init visible

    for (int lay = 0; lay < 3; lay++) {
        const int nch = (lay == 0) ? 16 : 64;
        for (int ch = 0; ch < nch; ch++, gc++) {
            // ---- producer (warp 0): issue chunk gc+NSTAGE-1 ----
            if (w == 0) {
                const int pg = gc + NSTAGE - 1;
                if (pg < NCH64) {
                    MBAR_WAIT(sb + SM_EMPTY + 8 * ps, ppar);
                    if (lane == 0) {
                        MBAR_EXPECT_TX(sb + SM_FULL + 8 * ps, CHUNK_B);
                        bulk_copy(sb + SM_W + (uint32_t)ps * CHUNK_B,
                                  g_Wp + (size_t)pg * CHUNK_H,
                                  sb + SM_FULL + 8 * ps);
                    }
                    if (++ps == NSTAGE) { ps = 0; ppar ^= 1; }
                }
            }

            // ---- consumer: wait chunk gc ----
            MBAR_WAIT(sb + SM_FULL + 8 * cs, cpar);
            const uint32_t wbu = sb + SM_W + (uint32_t)cs * CHUNK_B + lm_base;

            // h values (fp16) for this chunk's two k-rows, 4 n-rows
            uint32_t hv0 = *(const uint32_t*)(hrow0 + 2 * ch);
            uint32_t hv1 = *(const uint32_t*)(hrow1 + 2 * ch);
            uint32_t hv2 = *(const uint32_t*)(hrow2 + 2 * ch);
            uint32_t hv3 = *(const uint32_t*)(hrow3 + 2 * ch);
            __half2 p0 = *reinterpret_cast<__half2*>(&hv0);
            __half2 p1 = *reinterpret_cast<__half2*>(&hv1);
            __half2 p2 = *reinterpret_cast<__half2*>(&hv2);
            __half2 p3 = *reinterpret_cast<__half2*>(&hv3);
            __half2 hb[4][2];
            hb[0][0] = __half2half2(__low2half(p0));
            hb[0][1] = __half2half2(__high2half(p0));
            hb[1][0] = __half2half2(__low2half(p1));
            hb[1][1] = __half2half2(__high2half(p1));
            hb[2][0] = __half2half2(__low2half(p2));
            hb[2][1] = __half2half2(__high2half(p2));
            hb[3][0] = __half2half2(__low2half(p3));
            hb[3][1] = __half2half2(__high2half(p3));

#pragma unroll
            for (int sp = 0; sp < 4; sp++) {
                const int sub = sp >> 1;     // which k-row of the pair
                const int sh  = sp & 1;      // m half: [0,16) or [16,32)
                uint32_t a00 = h2u(__hmul2(hb[0][sub], x0h[0][2 * sh]));
                uint32_t a01 = h2u(__hmul2(hb[1][sub], x0h[1][2 * sh]));
                uint32_t a02 = h2u(__hmul2(hb[0][sub], x0h[0][2 * sh + 1]));
                uint32_t a03 = h2u(__hmul2(hb[1][sub], x0h[1][2 * sh + 1]));
                uint32_t a10 = h2u(__hmul2(hb[2][sub], x0h[2][2 * sh]));
                uint32_t a11 = h2u(__hmul2(hb[3][sub], x0h[3][2 * sh]));
                uint32_t a12 = h2u(__hmul2(hb[2][sub], x0h[2][2 * sh + 1]));
                uint32_t a13 = h2u(__hmul2(hb[3][sub], x0h[3][2 * sh + 1]));
                const uint32_t lma = wbu + (uint32_t)sub * 10240u +
                                     (uint32_t)sh * 32u;
#pragma unroll
                for (int g = 0; g < 4; g++) {
                    uint32_t b[4];
                    ldsm_x4(b, lma + (uint32_t)g * 1280);
                    mma16816(acc[2 * g],         a00, a01, a02, a03, b[0], b[1]);
                    mma16816(acc[2 * g + 1],     a00, a01, a02, a03, b[2], b[3]);
                    mma16816(acc[8 + 2 * g],     a10, a11, a12, a13, b[0], b[1]);
                    mma16816(acc[8 + 2 * g + 1], a10, a11, a12, a13, b[2], b[3]);
                }
            }

            // done with this stage
            if (lane == 0) MBAR_ARRIVE(sb + SM_EMPTY + 8 * cs);
            if (++cs == NSTAGE) { cs = 0; cpar ^= 1; }
        }

        // -------- epilogue --------
        __syncthreads();   // all warps done reading h for this layer
        {
            const float* biasS = (const float*)(smemc + SM_BIAS) + lay * 128;
            const float* lwS   = (const float*)(smemc + SM_LW) + lay * 128;
            float sc = 0.0f;
#pragma unroll
            for (int T = 0; T < 2; T++) {
                __half* ha  = T ? hrow2 : hrow0;
                __half* hc  = T ? hrow3 : hrow1;
#pragma unroll
                for (int go = 0; go < 8; go++) {
                    const int t = 8 * T + go;
                    const int o = 64 * wo + 8 * go + 2 * q;
                    const float bv0 = biasS[o], bv1 = biasS[o + 1];
                    float v00 = fmaxf(acc[t][0] + bv0, 0.0f);
                    float v01 = fmaxf(acc[t][1] + bv1, 0.0f);
                    float v10 = fmaxf(acc[t][2] + bv0, 0.0f);
                    float v11 = fmaxf(acc[t][3] + bv1, 0.0f);
                    sc += (v00 + v10) * lwS[o] + (v01 + v11) * lwS[o + 1];
                    if (lay < 2) {
                        *(__half2*)(ha + o) = __floats2half2_rn(v00, v01);
                        *(__half2*)(hc + o) = __floats2half2_rn(v10, v11);
                    }
                    acc[t][0] = acc[t][1] = acc[t][2] = acc[t][3] = 0.0f;
                }
            }
            score += sc;
        }
        __syncthreads();   // new h visible before next layer's reads
    }

    // warp-reduce score, accumulate per-batch
#pragma unroll
    for (int off = 16; off; off >>= 1)
        score += __shfl_xor_sync(0xFFFFFFFFu, score, off);
    if (lane == 0) atomicAdd((float*)(smemc + SM_SCORE) + bl, score);
    __syncthreads();

    if (tid < 4) outp[b_base + tid] = ((float*)(smemc + SM_SCORE))[tid] + lbp[0];
}

extern "C" void kernel_launch(void* const* d_in, const int* in_sizes, int n_in,
                              void* d_out, int out_size) {
    const float* x0 = (const float*)d_in[0];
    const float* W0 = (const float*)d_in[1];
    const float* b0 = (const float*)d_in[2];
    const float* W1 = (const float*)d_in[3];
    const float* b1 = (const float*)d_in[4];
    const float* W2 = (const float*)d_in[5];
    const float* b2 = (const float*)d_in[6];
    const float* lw = (const float*)d_in[7];
    const float* lb = (const float*)d_in[8];
    float* outp = (float*)d_out;

    constexpr int TOTV = NCH64 * (CHUNK_B / 16);   // 184320 uint4
    cin_pack<<<(TOTV + 1023) / 1024, 1024>>>(W0, W1, W2);

    static_assert(SMEM_BYTES <= 227 * 1024, "smem");
    cudaFuncSetAttribute(cin_main, cudaFuncAttributeMaxDynamicSharedMemorySize,
                         SMEM_BYTES);
    cin_main<<<NCTA, THREADS, SMEM_BYTES>>>(x0, b0, b1, b2, lw, lb, outp);
}